// round 14
// baseline (speedup 1.0000x reference)
#include <cuda_runtime.h>
#include <cuda_fp16.h>
#include <math.h>
#include <stdint.h>

// Problem constants
#define B_  128
#define T_  64
#define F_  2048
#define N_  1024
#define H_  1024
#define C_  22
#define G4  (4 * H_)   // 4096
#define NBLK 128       // persistent recurrence blocks

// ---------------- scratch (static device globals; no allocation) ----------------
__device__ __half g_z  [(size_t)B_ * T_ * N_];      // [8192, 1024] fp16
__device__ float  g_xg [(size_t)B_ * T_ * G4];      // [B, T, 4096] fp32
__device__ __half g_h0 [(size_t)B_ * H_];           // zero initial hidden (fp16)
__device__ __half g_hs [(size_t)T_ * B_ * H_];      // [T, B, H] fp16 (h history)
__device__ __half g_xh [(size_t)B_ * T_ * F_];      // fp16 x
__device__ __half g_w1h[(size_t)N_ * F_];           // fp16 W1
__device__ __half g_wih[(size_t)G4 * N_];           // fp16 W_ih
__device__ __half g_wch[24 * H_];                   // fp16 Wc padded to 24 rows
__device__ unsigned g_cnt[2][4];                    // [rowHalf][chunk] RAW counters

// fast activations: __fdividef = mul-by-rcp.approx (err ~2^-22), __expf = MUFU
__device__ __forceinline__ float sigmoidf_(float x) {
    return __fdividef(1.f, 1.f + __expf(-x));
}
__device__ __forceinline__ float fast_tanh(float x) {
    return 1.f - __fdividef(2.f, __expf(2.f * x) + 1.f);
}
__device__ __forceinline__ uint32_t packh2(float a, float b) {
    __half2 h = __floats2half2_rn(a, b);
    return *reinterpret_cast<uint32_t*>(&h);
}
__device__ __forceinline__ void mma_f16(float* acc, uint32_t a0, uint32_t a1,
                                        uint32_t a2, uint32_t a3,
                                        uint32_t b0, uint32_t b1)
{
    asm volatile(
        "mma.sync.aligned.m16n8k16.row.col.f32.f16.f16.f32 "
        "{%0,%1,%2,%3},{%4,%5,%6,%7},{%8,%9},{%0,%1,%2,%3};"
        : "+f"(acc[0]), "+f"(acc[1]), "+f"(acc[2]), "+f"(acc[3])
        : "r"(a0), "r"(a1), "r"(a2), "r"(a3), "r"(b0), "r"(b1));
}
#define LDSM4(r0, r1, r2, r3, addr)                                         \
    asm volatile("ldmatrix.sync.aligned.m8n8.x4.shared.b16 {%0,%1,%2,%3}, [%4];" \
                 : "=r"(r0), "=r"(r1), "=r"(r2), "=r"(r3) : "r"(addr))

// ---------------- fp32 -> fp16 convert ----------------
__global__ void to_half(const float4* __restrict__ in,
                        __half2* __restrict__ out, int n4)
{
    int i = blockIdx.x * blockDim.x + threadIdx.x;
    if (i >= n4) return;
    float4 v = in[i];
    out[2 * i]     = __floats2half2_rn(v.x, v.y);
    out[2 * i + 1] = __floats2half2_rn(v.z, v.w);
}
__global__ void prep_wc(const float* __restrict__ Wc, __half* __restrict__ out)
{
    int c = blockIdx.x;   // 0..23
    for (int k = threadIdx.x; k < H_; k += blockDim.x)
        out[c * H_ + k] = (c < C_) ? __float2half(Wc[(size_t)c * H_ + k])
                                   : __float2half(0.f);
}

// ============================================================================
// fp16 NT GEMM (mma.sync m16n8k16, ldmatrix): C[m,n]=sum_k A[m,k]*B[n,k](+bias)
// BM=128, BN=256, BK=64 halfs, 256 threads (8 warps 2x4, each 64x64), 3-stage,
// 1 CTA/SM, ONE sync per kb.  Halved smem-fragment traffic per FLOP.
// epi: 0 = +bias, write fp32 ; 1 = relu(+bias), write fp16
// ============================================================================
#define GBK 64
#define GSTR 72                        // halfs per smem row (144 B, bank-free)
#define GSTA_BYTES (128 * GSTR * 2)    // 18432 (A: 128 rows)
#define GSTB_BYTES (256 * GSTR * 2)    // 36864 (B: 256 rows)
#define GSTAGE_BYTES (GSTA_BYTES + GSTB_BYTES)  // 55296
#define GSTAGES 3
#define GEMM_SMEM (GSTAGES * GSTAGE_BYTES)      // 165888

__global__ void __launch_bounds__(256, 1)
gemm_h(const __half* __restrict__ A, const __half* __restrict__ Bw,
       const float* __restrict__ bias, void* __restrict__ Cout,
       int Ntot, int K, int epi)
{
    extern __shared__ __align__(16) char gsm[];
    const uint32_t smem_u32 = (uint32_t)__cvta_generic_to_shared(gsm);

    const int tid = threadIdx.x;
    const int lane = tid & 31, warp = tid >> 5;      // 8 warps
    const int bm = blockIdx.y * 128, bn = blockIdx.x * 256;
    const int wm = (warp & 1) * 64, wn = (warp >> 1) * 64;   // 2x4, 64x64 each
    const int grp = lane >> 2, tig = lane & 3;
    const int nk = K / GBK;

    // ldmatrix per-lane addressing
    const int aRow = ((lane >> 3) & 1) * 8 + (lane & 7);
    const int aCol = (lane >> 4) * 8;
    const int bRow = (lane & 7) + (lane >> 4) * 8;
    const int bCol = ((lane >> 3) & 1) * 8;

    float acc[4][8][4];
#pragma unroll
    for (int a = 0; a < 4; a++)
#pragma unroll
        for (int b = 0; b < 8; b++)
#pragma unroll
            for (int c = 0; c < 4; c++) acc[a][b][c] = 0.f;

    auto load_stage = [&](int kb, int buf) {
        const int k0 = kb * GBK;
        char* as = gsm + buf * GSTAGE_BYTES;
        char* bs = as + GSTA_BYTES;
        const int r = tid >> 3, p = tid & 7;   // 32 rows/pass, 8x16B pieces
#pragma unroll
        for (int w = 0; w < 4; w++) {
            int row = r + w * 32;
            unsigned da = (unsigned)__cvta_generic_to_shared(
                as + (row * GSTR + p * 8) * 2);
            asm volatile("cp.async.cg.shared.global [%0], [%1], 16;\n"
                         :: "r"(da), "l"(&A[(size_t)(bm + row) * K + k0 + p * 8]));
        }
#pragma unroll
        for (int w = 0; w < 8; w++) {
            int row = r + w * 32;
            unsigned db = (unsigned)__cvta_generic_to_shared(
                bs + (row * GSTR + p * 8) * 2);
            asm volatile("cp.async.cg.shared.global [%0], [%1], 16;\n"
                         :: "r"(db), "l"(&Bw[(size_t)(bn + row) * K + k0 + p * 8]));
        }
        asm volatile("cp.async.commit_group;\n");
    };

    load_stage(0, 0);
    load_stage(1, 1);

    for (int kb = 0; kb < nk; kb++) {
        if (kb + 1 < nk) asm volatile("cp.async.wait_group 1;\n");
        else             asm volatile("cp.async.wait_group 0;\n");
        __syncthreads();    // all warps done with compute(kb-1); stage kb ready

        if (kb + 2 < nk) load_stage(kb + 2, (kb + 2) % GSTAGES);

        const uint32_t a_b = smem_u32 + (kb % GSTAGES) * GSTAGE_BYTES;
        const uint32_t b_b = a_b + GSTA_BYTES;
#pragma unroll
        for (int s = 0; s < 4; s++) {
            const int koff = s * 16;
            uint32_t af[4][4], bf[8][2];
#pragma unroll
            for (int mt = 0; mt < 4; mt++) {
                uint32_t addr = a_b +
                    ((wm + mt * 16 + aRow) * GSTR + koff + aCol) * 2;
                LDSM4(af[mt][0], af[mt][1], af[mt][2], af[mt][3], addr);
            }
#pragma unroll
            for (int p = 0; p < 4; p++) {
                uint32_t addr = b_b +
                    ((wn + p * 16 + bRow) * GSTR + koff + bCol) * 2;
                LDSM4(bf[2 * p][0], bf[2 * p][1], bf[2 * p + 1][0],
                      bf[2 * p + 1][1], addr);
            }
#pragma unroll
            for (int mt = 0; mt < 4; mt++)
#pragma unroll
                for (int nt = 0; nt < 8; nt++)
                    mma_f16(acc[mt][nt], af[mt][0], af[mt][1], af[mt][2],
                            af[mt][3], bf[nt][0], bf[nt][1]);
        }
    }

    // epilogue
#pragma unroll
    for (int mt = 0; mt < 4; mt++) {
#pragma unroll
        for (int rh = 0; rh < 2; rh++) {
            int row = bm + wm + mt * 16 + grp + rh * 8;
#pragma unroll
            for (int nt = 0; nt < 8; nt++) {
                int col = bn + wn + nt * 8 + tig * 2;
                float v0 = acc[mt][nt][rh * 2 + 0] + bias[col];
                float v1 = acc[mt][nt][rh * 2 + 1] + bias[col + 1];
                if (epi == 1) {
                    v0 = fmaxf(v0, 0.f);
                    v1 = fmaxf(v1, 0.f);
                    __half* cp = (__half*)Cout;
                    *reinterpret_cast<__half2*>(&cp[(size_t)row * Ntot + col]) =
                        __floats2half2_rn(v0, v1);
                } else {
                    float* cp = (float*)Cout;
                    *reinterpret_cast<float2*>(&cp[(size_t)row * Ntot + col]) =
                        make_float2(v0, v1);
                }
            }
        }
    }
}

// ---------------- persistent LSTM recurrence (fp16, 64 rows x 64 cols) -------
// h history lives in g_hs (read h(t-1) = hs[t-1], write h(t) = hs[t]).
// RAW sync: per-chunk counters cnt[rowHalf][chunk]; chunk = 256 hidden cols
// = 16 producer CTAs. No WAR hazard (history), so no full barrier.
#define RT_STRIDE 264                        // halfs per staged row (528 B)
#define WF_SLOTS 16384                       // [k16=64][wg=2][nb=4][lane=32] uint2
#define WF_BYTES (WF_SLOTS * 8)              // 131072
#define HT_OFF   WF_BYTES
#define HT_CHUNK (64 * RT_STRIDE * 2)        // 33792 per buffer
#define HT_BYTES (2 * HT_CHUNK)              // 67584
#define REC_SMEM (WF_BYTES + HT_BYTES)       // 198656

__device__ __forceinline__ void stage_chunk_h(const __half* __restrict__ hsrc,
                                              char* __restrict__ dst,
                                              int chunk, int tid)
{
    const int p = tid & 31;       // 16B piece -> cols p*8..p*8+7 of 256
    const int r0 = tid >> 5;      // 0..7
    const __half* src = hsrc + chunk * 256 + p * 8;
#pragma unroll
    for (int w = 0; w < 8; w++) {
        int row = r0 + w * 8;
        unsigned da = (unsigned)__cvta_generic_to_shared(
            dst + (row * RT_STRIDE + p * 8) * 2);
        asm volatile("cp.async.cg.shared.global [%0], [%1], 16;\n"
                     :: "r"(da), "l"(src + (size_t)row * H_));
    }
    asm volatile("cp.async.commit_group;\n");
}

// thread0 acquire-poll until counter >= target (caller must __syncthreads after)
__device__ __forceinline__ void wait_cnt(const unsigned* p, unsigned target) {
    if (threadIdx.x == 0) {
        unsigned v;
        do {
            asm volatile("ld.acquire.gpu.global.u32 %0, [%1];"
                         : "=r"(v) : "l"(p));
        } while (v < target);
    }
}

__global__ void __launch_bounds__(256, 1)
lstm_persistent(const float* __restrict__ xg,
                const float* __restrict__ W_hh,
                const float* __restrict__ b_hh,
                const __half* __restrict__ h0,
                __half* __restrict__ hs)
{
    extern __shared__ __align__(16) char rsm[];
    uint2* Wf = (uint2*)rsm;                  // [k16][wg][nb][lane]
    const uint32_t rsm_u32 = (uint32_t)__cvta_generic_to_shared(rsm);

    const int tid  = threadIdx.x;
    const int lane = tid & 31;
    const int warp = tid >> 5;                // 0..7
    const int blk  = blockIdx.x;
    const int rowHalf = blk & 1;
    const int colBlk  = blk >> 1;             // 0..63
    const int grp  = lane >> 2;
    const int tig  = lane & 3;
    const int wm   = (warp & 3) * 16;         // local row tile
    const int wg   = warp >> 2;               // hidden group (0/1)
    const int row0 = rowHalf * 64 + wm;       // global batch row base
    const int hb0  = colBlk * 16 + wg * 8;    // hidden base for this warp
    const int myChunk = colBlk >> 4;          // which chunk this CTA produces

    // ldmatrix per-lane addressing for A (h) fragments
    const int aRow = wm + ((lane >> 3) & 1) * 8 + (lane & 7);
    const int aCol = (lane >> 4) * 8;

    // ---- one-time: W_hh slice as fp16 m16n8k16 B fragments ----
    for (int slot = tid; slot < WF_SLOTS; slot += 256) {
        int ls   = slot & 31;
        int idx2 = slot >> 5;
        int nb   = idx2 & 3;
        int wgf  = (idx2 >> 2) & 1;
        int k16  = idx2 >> 3;
        int gs = ls >> 2, ts = ls & 3;
        int gcol = nb * H_ + colBlk * 16 + wgf * 8 + gs;
        const float* wr = &W_hh[(size_t)gcol * H_ + k16 * 16 + 2 * ts];
        Wf[slot] = make_uint2(packh2(wr[0], wr[1]), packh2(wr[8], wr[9]));
    }

    float bh[8];
#pragma unroll
    for (int n = 0; n < 4; n++) {
        int gc = n * H_ + hb0 + 2 * tig;
        bh[2 * n]     = b_hh[gc];
        bh[2 * n + 1] = b_hh[gc + 1];
    }

    float cst[4];
#pragma unroll
    for (int i = 0; i < 4; i++) cst[i] = 0.f;

    __syncthreads();

    for (int t = 0; t < T_; t++) {
        const __half* hsrc = (t == 0)
            ? h0 + (size_t)rowHalf * 64 * H_
            : hs + ((size_t)(t - 1) * B_ + rowHalf * 64) * H_;

        // xg addends for this step (used ~5us later in pointwise)
        float xgv[16];
#pragma unroll
        for (int n = 0; n < 4; n++)
#pragma unroll
        for (int rh = 0; rh < 2; rh++) {
            int row = row0 + grp + rh * 8;
            size_t base = ((size_t)row * T_ + t) * G4 + n * H_ + hb0 + 2 * tig;
            float2 v = *reinterpret_cast<const float2*>(&xg[base]);
            xgv[(n * 2 + rh) * 2]     = v.x;
            xgv[(n * 2 + rh) * 2 + 1] = v.y;
        }

        float acc[4][4];
#pragma unroll
        for (int n = 0; n < 4; n++)
#pragma unroll
            for (int c = 0; c < 4; c++) acc[n][c] = 0.f;

        // RAW wait for chunk 0 producers, then stage it
        if (t > 0) wait_cnt(&g_cnt[rowHalf][0], 16u * (unsigned)t);
        __syncthreads();
        stage_chunk_h(hsrc, rsm + HT_OFF, 0, tid);

        for (int chunk = 0; chunk < 4; chunk++) {
            if (chunk + 1 < 4 && t > 0)
                wait_cnt(&g_cnt[rowHalf][chunk + 1], 16u * (unsigned)t);
            asm volatile("cp.async.wait_group 0;\n");
            __syncthreads();   // stage(chunk) visible; poll broadcast; buf free

            if (chunk + 1 < 4)
                stage_chunk_h(hsrc,
                    rsm + HT_OFF + ((chunk + 1) & 1) * HT_CHUNK,
                    chunk + 1, tid);

            const uint32_t hb_b = rsm_u32 + HT_OFF + (chunk & 1) * HT_CHUNK;
#pragma unroll
            for (int j = 0; j < 16; j++) {
                uint32_t a0, a1, a2, a3;
                uint32_t addr = hb_b + (aRow * RT_STRIDE + j * 16 + aCol) * 2;
                LDSM4(a0, a1, a2, a3, addr);
                const int k16 = chunk * 16 + j;
#pragma unroll
                for (int nb = 0; nb < 4; nb++) {
                    uint2 b = Wf[((k16 * 2 + wg) * 4 + nb) * 32 + lane];
                    mma_f16(acc[nb], a0, a1, a2, a3, b.x, b.y);
                }
            }
        }

        // fused LSTM pointwise (c-state in regs), write h(t) into hs[t]
#pragma unroll
        for (int rh = 0; rh < 2; rh++) {
            int row = row0 + grp + rh * 8;
            int hc  = hb0 + 2 * tig;
            float hpair[2];
#pragma unroll
            for (int cc = 0; cc < 2; cc++) {
                int ci = rh * 2 + cc;
                float gi = acc[0][ci] + xgv[(0 * 2 + rh) * 2 + cc] + bh[0 + cc];
                float gf = acc[1][ci] + xgv[(1 * 2 + rh) * 2 + cc] + bh[2 + cc];
                float gg = acc[2][ci] + xgv[(2 * 2 + rh) * 2 + cc] + bh[4 + cc];
                float go = acc[3][ci] + xgv[(3 * 2 + rh) * 2 + cc] + bh[6 + cc];
                float iv = sigmoidf_(gi);
                float fv = sigmoidf_(gf);
                float gv = fast_tanh(gg);
                float ov = sigmoidf_(go);
                float cn = fv * cst[ci] + iv * gv;
                cst[ci] = cn;
                hpair[cc] = ov * fast_tanh(cn);
            }
            __half2 hh = __floats2half2_rn(hpair[0], hpair[1]);
            *reinterpret_cast<__half2*>(&hs[((size_t)t * B_ + row) * H_ + hc]) = hh;
        }

        // release-signal: this CTA's 16 cols of hs[t] are written
        __syncthreads();
        if (tid == 0) {
            __threadfence();
            atomicAdd(&g_cnt[rowHalf][myChunk], 1u);
        }
    }
}

// ---------------- classifier (mma, Wc resident in smem) ----------------
#define CLS_WSTR 1032
#define CLS_ASTR 136
#define CLS_W_BYTES (24 * CLS_WSTR * 2)
#define CLS_A_OFF   CLS_W_BYTES
#define CLS_A_BYTES (2 * 64 * CLS_ASTR * 2)
#define CLS_SMEM (CLS_A_OFF + CLS_A_BYTES)

__global__ void __launch_bounds__(128, 1)
classifier_mma(const __half* __restrict__ hs,
               const __half* __restrict__ wch,
               const float* __restrict__ bc,
               float* __restrict__ out)
{
    extern __shared__ __align__(16) char csm[];
    const uint32_t csm_u32 = (uint32_t)__cvta_generic_to_shared(csm);
    __half* Wcs = (__half*)csm;

    const int tid = threadIdx.x;
    const int lane = tid & 31, warp = tid >> 5;
    const int b = blockIdx.x;
    const int grp = lane >> 2, tig = lane & 3;
    const int m0 = warp * 16;

    for (int i = tid; i < 24 * (H_ / 2); i += 128) {
        int c = i >> 9, kk = (i & 511) * 2;
        *reinterpret_cast<__half2*>(&Wcs[c * CLS_WSTR + kk]) =
            *reinterpret_cast<const __half2*>(&wch[c * H_ + kk]);
    }

    auto stage = [&](int chunk, int buf) {
        char* dst = csm + CLS_A_OFF + buf * 64 * CLS_ASTR * 2;
        const int p = tid & 15;
        const int r0 = tid >> 4;
#pragma unroll
        for (int w = 0; w < 8; w++) {
            int t = r0 + w * 8;
            unsigned da = (unsigned)__cvta_generic_to_shared(
                dst + (t * CLS_ASTR + p * 8) * 2);
            asm volatile("cp.async.cg.shared.global [%0], [%1], 16;\n"
                :: "r"(da),
                   "l"(&hs[((size_t)t * B_ + b) * H_ + chunk * 128 + p * 8]));
        }
        asm volatile("cp.async.commit_group;\n");
    };

    const int aRow = m0 + ((lane >> 3) & 1) * 8 + (lane & 7);
    const int aCol = (lane >> 4) * 8;

    float acc[3][4];
#pragma unroll
    for (int n = 0; n < 3; n++)
#pragma unroll
        for (int c = 0; c < 4; c++) acc[n][c] = 0.f;

    stage(0, 0);
    __syncthreads();

    for (int chunk = 0; chunk < 8; chunk++) {
        if (chunk + 1 < 8) {
            stage(chunk + 1, (chunk + 1) & 1);
            asm volatile("cp.async.wait_group 1;\n");
        } else {
            asm volatile("cp.async.wait_group 0;\n");
        }
        __syncthreads();

        const uint32_t a_b = csm_u32 + CLS_A_OFF + (chunk & 1) * 64 * CLS_ASTR * 2;
#pragma unroll
        for (int j = 0; j < 8; j++) {
            uint32_t a0, a1, a2, a3;
            uint32_t addr = a_b + (aRow * CLS_ASTR + j * 16 + aCol) * 2;
            LDSM4(a0, a1, a2, a3, addr);
            const int kbase = chunk * 128 + j * 16 + 2 * tig;
#pragma unroll
            for (int nt = 0; nt < 3; nt++) {
                int n = nt * 8 + grp;
                uint32_t b0 = *(const uint32_t*)&Wcs[n * CLS_WSTR + kbase];
                uint32_t b1 = *(const uint32_t*)&Wcs[n * CLS_WSTR + kbase + 8];
                mma_f16(acc[nt], a0, a1, a2, a3, b0, b1);
            }
        }
        __syncthreads();
    }

#pragma unroll
    for (int rh = 0; rh < 2; rh++) {
        int t = m0 + grp + rh * 8;
        size_t obase = ((size_t)b * T_ + t) * C_;
#pragma unroll
        for (int nt = 0; nt < 3; nt++) {
#pragma unroll
            for (int cc = 0; cc < 2; cc++) {
                int col = nt * 8 + 2 * tig + cc;
                if (col < C_)
                    out[obase + col] = acc[nt][rh * 2 + cc] + bc[col];
            }
        }
    }
}

// ---------------- launch ----------------
extern "C" void kernel_launch(void* const* d_in, const int* in_sizes, int n_in,
                              void* d_out, int out_size)
{
    (void)in_sizes; (void)n_in; (void)out_size;
    const float* x    = (const float*)d_in[0];
    const float* W1   = (const float*)d_in[1];
    const float* b1   = (const float*)d_in[2];
    const float* W_ih = (const float*)d_in[3];
    const float* b_ih = (const float*)d_in[4];
    const float* W_hh = (const float*)d_in[5];
    const float* b_hh = (const float*)d_in[6];
    const float* Wc   = (const float*)d_in[7];
    const float* bc   = (const float*)d_in[8];
    float* out = (float*)d_out;

    __half *z_p, *xh_p, *w1h_p, *wih_p, *h0_p, *hs_p, *wch_p;
    float *xg_p; unsigned* cnt_p;
    cudaGetSymbolAddress((void**)&z_p,   g_z);
    cudaGetSymbolAddress((void**)&xg_p,  g_xg);
    cudaGetSymbolAddress((void**)&h0_p,  g_h0);
    cudaGetSymbolAddress((void**)&hs_p,  g_hs);
    cudaGetSymbolAddress((void**)&xh_p,  g_xh);
    cudaGetSymbolAddress((void**)&w1h_p, g_w1h);
    cudaGetSymbolAddress((void**)&wih_p, g_wih);
    cudaGetSymbolAddress((void**)&wch_p, g_wch);
    cudaGetSymbolAddress((void**)&cnt_p, g_cnt);

    cudaMemsetAsync(cnt_p, 0, 8 * sizeof(unsigned));
    cudaMemsetAsync(h0_p, 0, (size_t)B_ * H_ * sizeof(__half));

    // 0) convert inputs to fp16
    {
        int n4 = B_ * T_ * F_ / 4;
        to_half<<<(n4 + 255) / 256, 256>>>((const float4*)x, (__half2*)xh_p, n4);
        n4 = N_ * F_ / 4;
        to_half<<<(n4 + 255) / 256, 256>>>((const float4*)W1, (__half2*)w1h_p, n4);
        n4 = G4 * N_ / 4;
        to_half<<<(n4 + 255) / 256, 256>>>((const float4*)W_ih, (__half2*)wih_p, n4);
        prep_wc<<<24, 256>>>(Wc, wch_p);
    }

    cudaFuncSetAttribute(gemm_h,
                         cudaFuncAttributeMaxDynamicSharedMemorySize, GEMM_SMEM);

    // 1) z = fp16(relu(x @ W1^T + b1)) : M=8192, N=1024, K=2048
    {
        dim3 grid(N_ / 256, (B_ * T_) / 128);
        gemm_h<<<grid, 256, GEMM_SMEM>>>(xh_p, w1h_p, b1, z_p, N_, F_, 1);
    }
    // 2) xg = z @ W_ih^T + b_ih (fp32 out) : M=8192, N=4096, K=1024
    {
        dim3 grid(G4 / 256, (B_ * T_) / 128);
        gemm_h<<<grid, 256, GEMM_SMEM>>>(z_p, wih_p, b_ih, xg_p, G4, N_, 0);
    }
    // 3) persistent recurrence (RAW-signaled, no grid barrier)
    cudaFuncSetAttribute(lstm_persistent,
                         cudaFuncAttributeMaxDynamicSharedMemorySize, REC_SMEM);
    lstm_persistent<<<NBLK, 256, REC_SMEM>>>(xg_p, W_hh, b_hh, h0_p, hs_p);

    // 4) classifier
    cudaFuncSetAttribute(classifier_mma,
                         cudaFuncAttributeMaxDynamicSharedMemorySize, CLS_SMEM);
    classifier_mma<<<B_, 128, CLS_SMEM>>>(hs_p, wch_p, bc, out);
}

// round 16
// speedup vs baseline: 1.0754x; 1.0754x over previous
#include <cuda_runtime.h>
#include <cuda_fp16.h>
#include <math.h>
#include <stdint.h>

// Problem constants
#define B_  128
#define T_  64
#define F_  2048
#define N_  1024
#define H_  1024
#define C_  22
#define G4  (4 * H_)   // 4096
#define NBLK 128       // persistent recurrence blocks

// ---------------- scratch (static device globals; no allocation) ----------------
__device__ __half g_z  [(size_t)B_ * T_ * N_];      // [8192, 1024] fp16
__device__ float  g_xg [(size_t)B_ * T_ * G4];      // [B, T, 4096] fp32
__device__ __half g_h0 [(size_t)B_ * H_];           // zero initial hidden (fp16)
__device__ __half g_hs [(size_t)T_ * B_ * H_];      // [T, B, H] fp16 (h history)
__device__ __half g_xh [(size_t)B_ * T_ * F_];      // fp16 x
__device__ __half g_w1h[(size_t)N_ * F_];           // fp16 W1
__device__ __half g_wih[(size_t)G4 * N_];           // fp16 W_ih
__device__ __half g_wch[24 * H_];                   // fp16 Wc padded to 24 rows
__device__ unsigned g_cnt[2][4];                    // [rowHalf][chunk] RAW counters

// fast activations: __fdividef = mul-by-rcp.approx (err ~2^-22), __expf = MUFU
__device__ __forceinline__ float sigmoidf_(float x) {
    return __fdividef(1.f, 1.f + __expf(-x));
}
__device__ __forceinline__ float fast_tanh(float x) {
    return 1.f - __fdividef(2.f, __expf(2.f * x) + 1.f);
}
__device__ __forceinline__ uint32_t packh2(float a, float b) {
    __half2 h = __floats2half2_rn(a, b);
    return *reinterpret_cast<uint32_t*>(&h);
}
__device__ __forceinline__ void mma_f16(float* acc, uint32_t a0, uint32_t a1,
                                        uint32_t a2, uint32_t a3,
                                        uint32_t b0, uint32_t b1)
{
    asm volatile(
        "mma.sync.aligned.m16n8k16.row.col.f32.f16.f16.f32 "
        "{%0,%1,%2,%3},{%4,%5,%6,%7},{%8,%9},{%0,%1,%2,%3};"
        : "+f"(acc[0]), "+f"(acc[1]), "+f"(acc[2]), "+f"(acc[3])
        : "r"(a0), "r"(a1), "r"(a2), "r"(a3), "r"(b0), "r"(b1));
}
#define LDSM4(r0, r1, r2, r3, addr)                                         \
    asm volatile("ldmatrix.sync.aligned.m8n8.x4.shared.b16 {%0,%1,%2,%3}, [%4];" \
                 : "=r"(r0), "=r"(r1), "=r"(r2), "=r"(r3) : "r"(addr))

// ---------------- fp32 -> fp16 convert ----------------
__global__ void to_half(const float4* __restrict__ in,
                        __half2* __restrict__ out, int n4)
{
    int i = blockIdx.x * blockDim.x + threadIdx.x;
    if (i >= n4) return;
    float4 v = in[i];
    out[2 * i]     = __floats2half2_rn(v.x, v.y);
    out[2 * i + 1] = __floats2half2_rn(v.z, v.w);
}
__global__ void prep_wc(const float* __restrict__ Wc, __half* __restrict__ out)
{
    int c = blockIdx.x;   // 0..23
    for (int k = threadIdx.x; k < H_; k += blockDim.x)
        out[c * H_ + k] = (c < C_) ? __float2half(Wc[(size_t)c * H_ + k])
                                   : __float2half(0.f);
}

// ============================================================================
// fp16 NT GEMM (mma.sync m16n8k16, ldmatrix): C[m,n]=sum_k A[m,k]*B[n,k](+bias)
// BM=BN=128, BK=64 halfs, 256 threads (8 warps 2x4, each 64x32), 3-stage,
// 2 CTAs/SM, ONE sync per kb.   (R13 champion config — do not touch)
// epi: 0 = +bias, write fp32 ; 1 = relu(+bias), write fp16
// ============================================================================
#define GBK 64
#define GSTR 72                       // halfs per smem row (144 B, bank-free)
#define GST_BYTES (128 * GSTR * 2)    // 18432 per matrix per stage
#define GSTAGE_BYTES (2 * GST_BYTES)  // 36864
#define GSTAGES 3
#define GEMM_SMEM (GSTAGES * GSTAGE_BYTES)  // 110592

__global__ void __launch_bounds__(256, 2)
gemm_h(const __half* __restrict__ A, const __half* __restrict__ Bw,
       const float* __restrict__ bias, void* __restrict__ Cout,
       int Ntot, int K, int epi)
{
    extern __shared__ __align__(16) char gsm[];
    const uint32_t smem_u32 = (uint32_t)__cvta_generic_to_shared(gsm);

    const int tid = threadIdx.x;
    const int lane = tid & 31, warp = tid >> 5;
    const int bm = blockIdx.y * 128, bn = blockIdx.x * 128;
    const int wm = (warp & 1) * 64, wn = (warp >> 1) * 32;
    const int grp = lane >> 2, tig = lane & 3;
    const int nk = K / GBK;

    const int aRow = ((lane >> 3) & 1) * 8 + (lane & 7);
    const int aCol = (lane >> 4) * 8;
    const int bRow = (lane & 7) + (lane >> 4) * 8;
    const int bCol = ((lane >> 3) & 1) * 8;

    float acc[4][4][4];
#pragma unroll
    for (int a = 0; a < 4; a++)
#pragma unroll
        for (int b = 0; b < 4; b++)
#pragma unroll
            for (int c = 0; c < 4; c++) acc[a][b][c] = 0.f;

    auto load_stage = [&](int kb, int buf) {
        const int k0 = kb * GBK;
        char* as = gsm + buf * GSTAGE_BYTES;
        char* bs = as + GST_BYTES;
        const int r = tid >> 3, p = tid & 7;
#pragma unroll
        for (int w = 0; w < 4; w++) {
            int row = r + w * 32;
            unsigned da = (unsigned)__cvta_generic_to_shared(
                as + (row * GSTR + p * 8) * 2);
            asm volatile("cp.async.cg.shared.global [%0], [%1], 16;\n"
                         :: "r"(da), "l"(&A[(size_t)(bm + row) * K + k0 + p * 8]));
            unsigned db = (unsigned)__cvta_generic_to_shared(
                bs + (row * GSTR + p * 8) * 2);
            asm volatile("cp.async.cg.shared.global [%0], [%1], 16;\n"
                         :: "r"(db), "l"(&Bw[(size_t)(bn + row) * K + k0 + p * 8]));
        }
        asm volatile("cp.async.commit_group;\n");
    };

    load_stage(0, 0);
    load_stage(1, 1);

    for (int kb = 0; kb < nk; kb++) {
        if (kb + 1 < nk) asm volatile("cp.async.wait_group 1;\n");
        else             asm volatile("cp.async.wait_group 0;\n");
        __syncthreads();

        if (kb + 2 < nk) load_stage(kb + 2, (kb + 2) % GSTAGES);

        const uint32_t a_b = smem_u32 + (kb % GSTAGES) * GSTAGE_BYTES;
        const uint32_t b_b = a_b + GST_BYTES;
#pragma unroll
        for (int s = 0; s < 4; s++) {
            const int koff = s * 16;
            uint32_t af[4][4], bf[4][2];
#pragma unroll
            for (int mt = 0; mt < 4; mt++) {
                uint32_t addr = a_b +
                    ((wm + mt * 16 + aRow) * GSTR + koff + aCol) * 2;
                LDSM4(af[mt][0], af[mt][1], af[mt][2], af[mt][3], addr);
            }
#pragma unroll
            for (int p = 0; p < 2; p++) {
                uint32_t addr = b_b +
                    ((wn + p * 16 + bRow) * GSTR + koff + bCol) * 2;
                LDSM4(bf[2 * p][0], bf[2 * p][1], bf[2 * p + 1][0],
                      bf[2 * p + 1][1], addr);
            }
#pragma unroll
            for (int mt = 0; mt < 4; mt++)
#pragma unroll
                for (int nt = 0; nt < 4; nt++)
                    mma_f16(acc[mt][nt], af[mt][0], af[mt][1], af[mt][2],
                            af[mt][3], bf[nt][0], bf[nt][1]);
        }
    }

#pragma unroll
    for (int mt = 0; mt < 4; mt++) {
#pragma unroll
        for (int rh = 0; rh < 2; rh++) {
            int row = bm + wm + mt * 16 + grp + rh * 8;
#pragma unroll
            for (int nt = 0; nt < 4; nt++) {
                int col = bn + wn + nt * 8 + tig * 2;
                float v0 = acc[mt][nt][rh * 2 + 0] + bias[col];
                float v1 = acc[mt][nt][rh * 2 + 1] + bias[col + 1];
                if (epi == 1) {
                    v0 = fmaxf(v0, 0.f);
                    v1 = fmaxf(v1, 0.f);
                    __half* cp = (__half*)Cout;
                    *reinterpret_cast<__half2*>(&cp[(size_t)row * Ntot + col]) =
                        __floats2half2_rn(v0, v1);
                } else {
                    float* cp = (float*)Cout;
                    *reinterpret_cast<float2*>(&cp[(size_t)row * Ntot + col]) =
                        make_float2(v0, v1);
                }
            }
        }
    }
}

// ---------------- persistent LSTM recurrence (fp16, split-k warps) ----------
// CTA: 64 rows x 64 gate cols. 8 warps = 2 row-tiles(32) x 2 hidden-groups x
// 2 k-halves. Each warp m32n32 over half the k16 range -> Wf smem traffic
// halved vs 16-row warps. wk pair reduced through smem; pointwise on wk=0.
#define RT_STRIDE 264                        // halfs per staged row (528 B)
#define WF_SLOTS 16384                       // [k16=64][wg=2][nb=4][lane=32] uint2
#define WF_BYTES (WF_SLOTS * 8)              // 131072
#define HT_OFF   WF_BYTES
#define HT_CHUNK (64 * RT_STRIDE * 2)        // 33792 per buffer
#define HT_BYTES (2 * HT_CHUNK)              // 67584
#define REC_SMEM (WF_BYTES + HT_BYTES)       // 198656

__device__ __forceinline__ void stage_chunk_h(const __half* __restrict__ hsrc,
                                              char* __restrict__ dst,
                                              int chunk, int tid)
{
    const int p = tid & 31;       // 16B piece -> cols p*8..p*8+7 of 256
    const int r0 = tid >> 5;      // 0..7
    const __half* src = hsrc + chunk * 256 + p * 8;
#pragma unroll
    for (int w = 0; w < 8; w++) {
        int row = r0 + w * 8;
        unsigned da = (unsigned)__cvta_generic_to_shared(
            dst + (row * RT_STRIDE + p * 8) * 2);
        asm volatile("cp.async.cg.shared.global [%0], [%1], 16;\n"
                     :: "r"(da), "l"(src + (size_t)row * H_));
    }
    asm volatile("cp.async.commit_group;\n");
}

__device__ __forceinline__ void wait_cnt(const unsigned* p, unsigned target) {
    if (threadIdx.x == 0) {
        unsigned v;
        do {
            asm volatile("ld.acquire.gpu.global.u32 %0, [%1];"
                         : "=r"(v) : "l"(p));
        } while (v < target);
    }
}

__global__ void __launch_bounds__(256, 1)
lstm_persistent(const float* __restrict__ xg,
                const float* __restrict__ W_hh,
                const float* __restrict__ b_hh,
                const __half* __restrict__ h0,
                __half* __restrict__ hs)
{
    extern __shared__ __align__(16) char rsm[];
    uint2* Wf = (uint2*)rsm;                  // [k16][wg][nb][lane]
    const uint32_t rsm_u32 = (uint32_t)__cvta_generic_to_shared(rsm);

    const int tid  = threadIdx.x;
    const int lane = tid & 31;
    const int warp = tid >> 5;                // 0..7
    const int blk  = blockIdx.x;
    const int rowHalf = blk & 1;
    const int colBlk  = blk >> 1;             // 0..63
    const int grp  = lane >> 2;
    const int tig  = lane & 3;
    const int wr   = warp & 1;                // row tile (0/1), 32 rows each
    const int wg   = (warp >> 1) & 1;         // hidden group (0/1)
    const int wk   = warp >> 2;               // k half (0/1)
    const int wm   = wr * 32;                 // local row tile base
    const int row0 = rowHalf * 64 + wm;       // global batch row base
    const int hb0  = colBlk * 16 + wg * 8;    // hidden base for this warp
    const int myChunk = colBlk >> 4;          // which chunk this CTA produces
    const int pairId = wr * 2 + wg;           // reduction slot

    // ldmatrix per-lane addressing for A (h) fragments
    const int aRow = wm + ((lane >> 3) & 1) * 8 + (lane & 7);
    const int aCol = (lane >> 4) * 8;

    // ---- one-time: W_hh slice as fp16 m16n8k16 B fragments ----
    for (int slot = tid; slot < WF_SLOTS; slot += 256) {
        int ls   = slot & 31;
        int idx2 = slot >> 5;
        int nb   = idx2 & 3;
        int wgf  = (idx2 >> 2) & 1;
        int k16  = idx2 >> 3;
        int gs = ls >> 2, ts = ls & 3;
        int gcol = nb * H_ + colBlk * 16 + wgf * 8 + gs;
        const float* wr_ = &W_hh[(size_t)gcol * H_ + k16 * 16 + 2 * ts];
        Wf[slot] = make_uint2(packh2(wr_[0], wr_[1]), packh2(wr_[8], wr_[9]));
    }

    float bh[8];
#pragma unroll
    for (int n = 0; n < 4; n++) {
        int gc = n * H_ + hb0 + 2 * tig;
        bh[2 * n]     = b_hh[gc];
        bh[2 * n + 1] = b_hh[gc + 1];
    }

    float cst[8];    // [mt(2)][rh(2)][cc(2)] for wk==0 threads
#pragma unroll
    for (int i = 0; i < 8; i++) cst[i] = 0.f;

    __syncthreads();

    for (int t = 0; t < T_; t++) {
        const __half* hsrc = (t == 0)
            ? h0 + (size_t)rowHalf * 64 * H_
            : hs + ((size_t)(t - 1) * B_ + rowHalf * 64) * H_;

        // xg addends for this step (only wk==0 warps need them)
        float xgv[32];
        if (wk == 0) {
#pragma unroll
            for (int mt = 0; mt < 2; mt++)
#pragma unroll
            for (int n = 0; n < 4; n++)
#pragma unroll
            for (int rh = 0; rh < 2; rh++) {
                int row = row0 + mt * 16 + grp + rh * 8;
                size_t base = ((size_t)row * T_ + t) * G4 + n * H_ +
                              hb0 + 2 * tig;
                float2 v = *reinterpret_cast<const float2*>(&xg[base]);
                int o = ((mt * 4 + n) * 2 + rh) * 2;
                xgv[o] = v.x; xgv[o + 1] = v.y;
            }
        }

        float acc[2][4][4];
#pragma unroll
        for (int mt = 0; mt < 2; mt++)
#pragma unroll
        for (int n = 0; n < 4; n++)
#pragma unroll
            for (int c = 0; c < 4; c++) acc[mt][n][c] = 0.f;

        // RAW wait for chunk 0 producers, then stage it
        if (t > 0) wait_cnt(&g_cnt[rowHalf][0], 16u * (unsigned)t);
        __syncthreads();
        stage_chunk_h(hsrc, rsm + HT_OFF, 0, tid);

        for (int chunk = 0; chunk < 4; chunk++) {
            if (chunk + 1 < 4 && t > 0)
                wait_cnt(&g_cnt[rowHalf][chunk + 1], 16u * (unsigned)t);
            asm volatile("cp.async.wait_group 0;\n");
            __syncthreads();   // stage(chunk) visible; poll broadcast; buf free

            if (chunk + 1 < 4)
                stage_chunk_h(hsrc,
                    rsm + HT_OFF + ((chunk + 1) & 1) * HT_CHUNK,
                    chunk + 1, tid);

            const uint32_t hb_b = rsm_u32 + HT_OFF + (chunk & 1) * HT_CHUNK;
#pragma unroll
            for (int j = 0; j < 8; j++) {
                const int kk = wk * 8 + j;     // k16 within chunk (this warp's half)
                uint32_t a0, a1, a2, a3, a4, a5, a6, a7;
                uint32_t ad0 = hb_b + ((aRow)      * RT_STRIDE + kk * 16 + aCol) * 2;
                uint32_t ad1 = hb_b + ((aRow + 16) * RT_STRIDE + kk * 16 + aCol) * 2;
                LDSM4(a0, a1, a2, a3, ad0);
                LDSM4(a4, a5, a6, a7, ad1);
                const int k16 = chunk * 16 + kk;
#pragma unroll
                for (int nb = 0; nb < 4; nb++) {
                    uint2 b = Wf[((k16 * 2 + wg) * 4 + nb) * 32 + lane];
                    mma_f16(acc[0][nb], a0, a1, a2, a3, b.x, b.y);
                    mma_f16(acc[1][nb], a4, a5, a6, a7, b.x, b.y);
                }
            }
        }

        // ---- cross-wk reduction through smem (stage buffers idle now) ----
        float* red = (float*)(rsm + HT_OFF);
        __syncthreads();
        if (wk == 1) {
#pragma unroll
            for (int mt = 0; mt < 2; mt++)
#pragma unroll
            for (int nb = 0; nb < 4; nb++)
#pragma unroll
            for (int q = 0; q < 4; q++)
                red[pairId * 1024 + ((mt * 4 + nb) * 4 + q) * 32 + lane] =
                    acc[mt][nb][q];
        }
        __syncthreads();

        if (wk == 0) {
#pragma unroll
            for (int mt = 0; mt < 2; mt++)
#pragma unroll
            for (int nb = 0; nb < 4; nb++)
#pragma unroll
            for (int q = 0; q < 4; q++)
                acc[mt][nb][q] +=
                    red[pairId * 1024 + ((mt * 4 + nb) * 4 + q) * 32 + lane];

            // fused LSTM pointwise (c-state in regs), write h(t) into hs[t]
#pragma unroll
            for (int mt = 0; mt < 2; mt++)
#pragma unroll
            for (int rh = 0; rh < 2; rh++) {
                int row = row0 + mt * 16 + grp + rh * 8;
                int hc  = hb0 + 2 * tig;
                float hpair[2];
#pragma unroll
                for (int cc = 0; cc < 2; cc++) {
                    int ci = rh * 2 + cc;
                    float gi = acc[mt][0][ci] + xgv[((mt*4+0)*2+rh)*2+cc] + bh[0+cc];
                    float gf = acc[mt][1][ci] + xgv[((mt*4+1)*2+rh)*2+cc] + bh[2+cc];
                    float gg = acc[mt][2][ci] + xgv[((mt*4+2)*2+rh)*2+cc] + bh[4+cc];
                    float go = acc[mt][3][ci] + xgv[((mt*4+3)*2+rh)*2+cc] + bh[6+cc];
                    float iv = sigmoidf_(gi);
                    float fv = sigmoidf_(gf);
                    float gv = fast_tanh(gg);
                    float ov = sigmoidf_(go);
                    int csi = mt * 4 + rh * 2 + cc;
                    float cn = fv * cst[csi] + iv * gv;
                    cst[csi] = cn;
                    hpair[cc] = ov * fast_tanh(cn);
                }
                __half2 hh = __floats2half2_rn(hpair[0], hpair[1]);
                *reinterpret_cast<__half2*>(
                    &hs[((size_t)t * B_ + row) * H_ + hc]) = hh;
            }
        }

        // release-signal: this CTA's 16 cols of hs[t] are written
        __syncthreads();
        if (tid == 0) {
            __threadfence();
            atomicAdd(&g_cnt[rowHalf][myChunk], 1u);
        }
    }
}

// ---------------- classifier (mma, Wc resident in smem) ----------------
#define CLS_WSTR 1032
#define CLS_ASTR 136
#define CLS_W_BYTES (24 * CLS_WSTR * 2)
#define CLS_A_OFF   CLS_W_BYTES
#define CLS_A_BYTES (2 * 64 * CLS_ASTR * 2)
#define CLS_SMEM (CLS_A_OFF + CLS_A_BYTES)

__global__ void __launch_bounds__(128, 1)
classifier_mma(const __half* __restrict__ hs,
               const __half* __restrict__ wch,
               const float* __restrict__ bc,
               float* __restrict__ out)
{
    extern __shared__ __align__(16) char csm[];
    const uint32_t csm_u32 = (uint32_t)__cvta_generic_to_shared(csm);
    __half* Wcs = (__half*)csm;

    const int tid = threadIdx.x;
    const int lane = tid & 31, warp = tid >> 5;
    const int b = blockIdx.x;
    const int grp = lane >> 2, tig = lane & 3;
    const int m0 = warp * 16;

    for (int i = tid; i < 24 * (H_ / 2); i += 128) {
        int c = i >> 9, kk = (i & 511) * 2;
        *reinterpret_cast<__half2*>(&Wcs[c * CLS_WSTR + kk]) =
            *reinterpret_cast<const __half2*>(&wch[c * H_ + kk]);
    }

    auto stage = [&](int chunk, int buf) {
        char* dst = csm + CLS_A_OFF + buf * 64 * CLS_ASTR * 2;
        const int p = tid & 15;
        const int r0 = tid >> 4;
#pragma unroll
        for (int w = 0; w < 8; w++) {
            int t = r0 + w * 8;
            unsigned da = (unsigned)__cvta_generic_to_shared(
                dst + (t * CLS_ASTR + p * 8) * 2);
            asm volatile("cp.async.cg.shared.global [%0], [%1], 16;\n"
                :: "r"(da),
                   "l"(&hs[((size_t)t * B_ + b) * H_ + chunk * 128 + p * 8]));
        }
        asm volatile("cp.async.commit_group;\n");
    };

    const int aRow = m0 + ((lane >> 3) & 1) * 8 + (lane & 7);
    const int aCol = (lane >> 4) * 8;

    float acc[3][4];
#pragma unroll
    for (int n = 0; n < 3; n++)
#pragma unroll
        for (int c = 0; c < 4; c++) acc[n][c] = 0.f;

    stage(0, 0);
    __syncthreads();

    for (int chunk = 0; chunk < 8; chunk++) {
        if (chunk + 1 < 8) {
            stage(chunk + 1, (chunk + 1) & 1);
            asm volatile("cp.async.wait_group 1;\n");
        } else {
            asm volatile("cp.async.wait_group 0;\n");
        }
        __syncthreads();

        const uint32_t a_b = csm_u32 + CLS_A_OFF + (chunk & 1) * 64 * CLS_ASTR * 2;
#pragma unroll
        for (int j = 0; j < 8; j++) {
            uint32_t a0, a1, a2, a3;
            uint32_t addr = a_b + (aRow * CLS_ASTR + j * 16 + aCol) * 2;
            LDSM4(a0, a1, a2, a3, addr);
            const int kbase = chunk * 128 + j * 16 + 2 * tig;
#pragma unroll
            for (int nt = 0; nt < 3; nt++) {
                int n = nt * 8 + grp;
                uint32_t b0 = *(const uint32_t*)&Wcs[n * CLS_WSTR + kbase];
                uint32_t b1 = *(const uint32_t*)&Wcs[n * CLS_WSTR + kbase + 8];
                mma_f16(acc[nt], a0, a1, a2, a3, b0, b1);
            }
        }
        __syncthreads();
    }

#pragma unroll
    for (int rh = 0; rh < 2; rh++) {
        int t = m0 + grp + rh * 8;
        size_t obase = ((size_t)b * T_ + t) * C_;
#pragma unroll
        for (int nt = 0; nt < 3; nt++) {
#pragma unroll
            for (int cc = 0; cc < 2; cc++) {
                int col = nt * 8 + 2 * tig + cc;
                if (col < C_)
                    out[obase + col] = acc[nt][rh * 2 + cc] + bc[col];
            }
        }
    }
}

// ---------------- launch ----------------
extern "C" void kernel_launch(void* const* d_in, const int* in_sizes, int n_in,
                              void* d_out, int out_size)
{
    (void)in_sizes; (void)n_in; (void)out_size;
    const float* x    = (const float*)d_in[0];
    const float* W1   = (const float*)d_in[1];
    const float* b1   = (const float*)d_in[2];
    const float* W_ih = (const float*)d_in[3];
    const float* b_ih = (const float*)d_in[4];
    const float* W_hh = (const float*)d_in[5];
    const float* b_hh = (const float*)d_in[6];
    const float* Wc   = (const float*)d_in[7];
    const float* bc   = (const float*)d_in[8];
    float* out = (float*)d_out;

    __half *z_p, *xh_p, *w1h_p, *wih_p, *h0_p, *hs_p, *wch_p;
    float *xg_p; unsigned* cnt_p;
    cudaGetSymbolAddress((void**)&z_p,   g_z);
    cudaGetSymbolAddress((void**)&xg_p,  g_xg);
    cudaGetSymbolAddress((void**)&h0_p,  g_h0);
    cudaGetSymbolAddress((void**)&hs_p,  g_hs);
    cudaGetSymbolAddress((void**)&xh_p,  g_xh);
    cudaGetSymbolAddress((void**)&w1h_p, g_w1h);
    cudaGetSymbolAddress((void**)&wih_p, g_wih);
    cudaGetSymbolAddress((void**)&wch_p, g_wch);
    cudaGetSymbolAddress((void**)&cnt_p, g_cnt);

    cudaMemsetAsync(cnt_p, 0, 8 * sizeof(unsigned));
    cudaMemsetAsync(h0_p, 0, (size_t)B_ * H_ * sizeof(__half));

    // 0) convert inputs to fp16
    {
        int n4 = B_ * T_ * F_ / 4;
        to_half<<<(n4 + 255) / 256, 256>>>((const float4*)x, (__half2*)xh_p, n4);
        n4 = N_ * F_ / 4;
        to_half<<<(n4 + 255) / 256, 256>>>((const float4*)W1, (__half2*)w1h_p, n4);
        n4 = G4 * N_ / 4;
        to_half<<<(n4 + 255) / 256, 256>>>((const float4*)W_ih, (__half2*)wih_p, n4);
        prep_wc<<<24, 256>>>(Wc, wch_p);
    }

    cudaFuncSetAttribute(gemm_h,
                         cudaFuncAttributeMaxDynamicSharedMemorySize, GEMM_SMEM);

    // 1) z = fp16(relu(x @ W1^T + b1)) : M=8192, N=1024, K=2048
    {
        dim3 grid(N_ / 128, (B_ * T_) / 128);
        gemm_h<<<grid, 256, GEMM_SMEM>>>(xh_p, w1h_p, b1, z_p, N_, F_, 1);
    }
    // 2) xg = z @ W_ih^T + b_ih (fp32 out) : M=8192, N=4096, K=1024
    {
        dim3 grid(G4 / 128, (B_ * T_) / 128);
        gemm_h<<<grid, 256, GEMM_SMEM>>>(z_p, wih_p, b_ih, xg_p, G4, N_, 0);
    }
    // 3) persistent recurrence (RAW-signaled, split-k warps)
    cudaFuncSetAttribute(lstm_persistent,
                         cudaFuncAttributeMaxDynamicSharedMemorySize, REC_SMEM);
    lstm_persistent<<<NBLK, 256, REC_SMEM>>>(xg_p, W_hh, b_hh, h0_p, hs_p);

    // 4) classifier
    cudaFuncSetAttribute(classifier_mma,
                         cudaFuncAttributeMaxDynamicSharedMemorySize, CLS_SMEM);
    classifier_mma<<<B_, 128, CLS_SMEM>>>(hs_p, wch_p, bc, out);
}